// round 11
// baseline (speedup 1.0000x reference)
#include <cuda_runtime.h>
#include <cuda_fp16.h>
#include <math_constants.h>
#include <cstdint>

#define TOKENS  32768
#define DIM     2048
#define NE      64
#define TOPK    6
#define MT      128                 // tokens per CTA
#define KCH     32                  // K per chunk
#define NCH     (DIM / KCH)         // 64
#define NTH     256
#define WSCALE_INV 0.03125f         // w pre-scaled by 32 in split kernel

// smem map (dynamic): x 3x16KB (2 fp16 terms x 8KB) | w 3x8KB | bias
#define OFFX    0
#define XBUF    16384
#define XT2     8192                // term-2 offset inside an x slot
#define OFFW    49152
#define WBUF    8192
#define OFFB    73728
#define SMEMSZ  73984

// pre-split (fp16, w*32), pre-swizzled weights: [term][chunk][64 experts x 64B]
__device__ __align__(16) unsigned char g_wsw[2][NCH][NE * KCH * 2];

__device__ __forceinline__ unsigned su32(const void* p) {
    return (unsigned)__cvta_generic_to_shared(p);
}
__device__ __forceinline__ void cp16(unsigned d, const void* s) {
    asm volatile("cp.async.cg.shared.global [%0], [%1], 16;" :: "r"(d), "l"(s));
}
// 64B-row XOR swizzle: bits[5:4] ^= bits[8:7]  (same one validated on the w tiles)
__device__ __forceinline__ unsigned sw64(unsigned off) {
    return off ^ (((off >> 7) & 3u) << 4);
}
// 2-term fp16 split of (f0,f1): p1 = rn(f), p2 = rn(f - p1)
__device__ __forceinline__ void split2h(float f0, float f1, unsigned& p1, unsigned& p2) {
    __half2 h1 = __floats2half2_rn(f0, f1);
    p1 = *(unsigned*)&h1;
    float2 g = __half22float2(h1);
    __half2 h2 = __floats2half2_rn(f0 - g.x, f1 - g.y);
    p2 = *(unsigned*)&h2;
}
__device__ __forceinline__ void ldsm4(unsigned b[4], unsigned addr) {
    asm volatile("ldmatrix.sync.aligned.m8n8.x4.shared.b16 {%0,%1,%2,%3}, [%4];"
                 : "=r"(b[0]), "=r"(b[1]), "=r"(b[2]), "=r"(b[3]) : "r"(addr));
}
// accumulate: C += A*B (fp16 in, fp32 acc)
__device__ __forceinline__ void mma16816(float* c, const unsigned* a,
                                         unsigned b0, unsigned b1) {
    asm volatile(
        "mma.sync.aligned.m16n8k16.row.col.f32.f16.f16.f32 "
        "{%0,%1,%2,%3}, {%4,%5,%6,%7}, {%8,%9}, {%0,%1,%2,%3};"
        : "+f"(c[0]), "+f"(c[1]), "+f"(c[2]), "+f"(c[3])
        : "r"(a[0]), "r"(a[1]), "r"(a[2]), "r"(a[3]), "r"(b0), "r"(b1));
}
// zero-start: C = A*B
__device__ __forceinline__ void mma16816_z(float* c, const unsigned* a,
                                           unsigned b0, unsigned b1) {
    asm volatile(
        "mma.sync.aligned.m16n8k16.row.col.f32.f16.f16.f32 "
        "{%0,%1,%2,%3}, {%4,%5,%6,%7}, {%8,%9}, {%10,%11,%12,%13};"
        : "=f"(c[0]), "=f"(c[1]), "=f"(c[2]), "=f"(c[3])
        : "r"(a[0]), "r"(a[1]), "r"(a[2]), "r"(a[3]), "r"(b0), "r"(b1),
          "f"(0.0f), "f"(0.0f), "f"(0.0f), "f"(0.0f));
}

// ---- pre-kernel: 2-term fp16 split of 32*w, ldmatrix-swizzled rows of 64B ----
__global__ void split_w_kernel(const float* __restrict__ w) {
    int idx = blockIdx.x * 256 + threadIdx.x;     // e*DIM + k, < 131072
    int e = idx >> 11, k = idx & (DIM - 1);
    float v = w[idx] * 32.0f;                     // exact scale, undone in epilogue
    __half h1 = __float2half_rn(v);
    float f1 = __half2float(h1);
    __half h2 = __float2half_rn(v - f1);
    int c = k >> 5, kk = k & (KCH - 1);
    unsigned off = ((unsigned)e << 6) | ((unsigned)kk << 1);
    unsigned sw = sw64(off);
    *(unsigned short*)&g_wsw[0][c][sw] = *(unsigned short*)&h1;
    *(unsigned short*)&g_wsw[1][c][sw] = *(unsigned short*)&h2;
}

__global__ __launch_bounds__(NTH, 2)
void gate_hmma_kernel(const float* __restrict__ x,
                      const float* __restrict__ bias,
                      float* __restrict__ out) {
    extern __shared__ unsigned char sm[];

    const int tid = threadIdx.x;
    const int wid = tid >> 5;
    const int L   = tid & 31;
    const int r4  = L >> 2;          // 0..7
    const int cq  = L & 3;           // 0..3
    const int t0  = blockIdx.x * MT;

    if (tid < NE) ((float*)(sm + OFFB))[tid] = bias[tid];

    // ---- x staging: thread owns (row, khalf); 16 fp32 -> 16 fp16 x2 terms ----
    const int srow = tid >> 1;                 // 0..127
    const int skh  = tid & 1;                  // 0..1 (k 0-15 / 16-31)
    const float4* xsrc = (const float4*)(x + (size_t)(t0 + srow) * DIM + skh * 16);
    const unsigned xsts0 = su32(sm + OFFX) + sw64(((unsigned)srow << 6) | (skh * 32));
    const unsigned xsts1 = su32(sm + OFFX) + sw64(((unsigned)srow << 6) | (skh * 32 + 16));

    // ---- w cp.async setup ----
    const unsigned char* wsrc[2]; unsigned wdst[2];
#pragma unroll
    for (int i = 0; i < 2; i++) {
        int u = tid + NTH * i;                 // 0..511 = 2 terms x 256 units
        int trm = u >> 8; unsigned o = (unsigned)(u & 255) << 4;
        wsrc[i] = &g_wsw[trm][0][o];
        wdst[i] = su32(sm + OFFW) + trm * 4096 + o;
    }

    // ---- A-ldsm per-lane address pieces ----
    const unsigned arow = (unsigned)(wid * 16 + (L & 7) + (((L >> 3) & 1) << 3)) << 6;
    const unsigned akb0 = ((L >> 4) & 1) * 16;     // + s*32 per step

    // fp32 running logits, drained every 2 chunks (validated chain depth 12)
    float run[8][4];
#pragma unroll
    for (int n = 0; n < 8; n++)
#pragma unroll
        for (int i = 0; i < 4; i++) run[n][i] = 0.0f;

    // ---- prologue ----
    float4 xr[4];
#pragma unroll
    for (int i = 0; i < 4; i++) xr[i] = xsrc[i];   // x chunk 0
    // w chunks 0,1 -> slots 0,1
#pragma unroll
    for (int sl = 0; sl < 2; sl++) {
#pragma unroll
        for (int i = 0; i < 2; i++) { cp16(wdst[i] + sl * WBUF, wsrc[i]); wsrc[i] += 4096; }
        asm volatile("cp.async.commit_group;");
    }
    // split+STS x chunk 0 -> slot 0
    {
        uint4 t1a, t1b, t2a, t2b;
        split2h(xr[0].x, xr[0].y, t1a.x, t2a.x); split2h(xr[0].z, xr[0].w, t1a.y, t2a.y);
        split2h(xr[1].x, xr[1].y, t1a.z, t2a.z); split2h(xr[1].z, xr[1].w, t1a.w, t2a.w);
        split2h(xr[2].x, xr[2].y, t1b.x, t2b.x); split2h(xr[2].z, xr[2].w, t1b.y, t2b.y);
        split2h(xr[3].x, xr[3].y, t1b.z, t2b.z); split2h(xr[3].z, xr[3].w, t1b.w, t2b.w);
        asm volatile("st.shared.v4.b32 [%0], {%1,%2,%3,%4};" :: "r"(xsts0),
                     "r"(t1a.x), "r"(t1a.y), "r"(t1a.z), "r"(t1a.w));
        asm volatile("st.shared.v4.b32 [%0], {%1,%2,%3,%4};" :: "r"(xsts1),
                     "r"(t1b.x), "r"(t1b.y), "r"(t1b.z), "r"(t1b.w));
        asm volatile("st.shared.v4.b32 [%0], {%1,%2,%3,%4};" :: "r"(xsts0 + XT2),
                     "r"(t2a.x), "r"(t2a.y), "r"(t2a.z), "r"(t2a.w));
        asm volatile("st.shared.v4.b32 [%0], {%1,%2,%3,%4};" :: "r"(xsts1 + XT2),
                     "r"(t2b.x), "r"(t2b.y), "r"(t2b.z), "r"(t2b.w));
    }
    // LDG x chunk 1
#pragma unroll
    for (int i = 0; i < 4; i++) xr[i] = xsrc[8 + i];   // +32 floats = +8 float4

    float cc[8][4];                          // 2-chunk tensor-core chains

    for (int ch = 0; ch < NCH; ch++) {
        if (ch < NCH - 1) {
            asm volatile("cp.async.wait_group 1;");
        } else {
            asm volatile("cp.async.wait_group 0;");
        }
        __syncthreads();   // w ch + x ch visible; slot (ch+1)%3 free for x STS

        // prefetch w chunk ch+2
        if (ch + 2 < NCH) {
#pragma unroll
            for (int i = 0; i < 2; i++) {
                cp16(wdst[i] + ((ch + 2) % 3) * WBUF, wsrc[i]); wsrc[i] += 4096;
            }
            asm volatile("cp.async.commit_group;");
        }

        const unsigned xb = su32(sm + OFFX) + (ch % 3) * XBUF;
        const unsigned wb = su32(sm + OFFW) + (ch % 3) * WBUF;
        const bool zstart = (ch & 1) == 0;

        // ---- compute chunk ch: A via ldmatrix, 3 products per C per k-step ----
#pragma unroll
        for (int s = 0; s < 2; s++) {
            unsigned a1[4], a2[4];
            unsigned asw = sw64(arow | (akb0 + s * 32));
            ldsm4(a1, xb + asw);
            ldsm4(a2, xb + XT2 + asw);

            const int m  = L >> 3;
            const int rr = L & 7;
#pragma unroll
            for (int p = 0; p < 4; p++) {
                int e = p * 16 + (m >> 1) * 8 + rr;
                unsigned off = ((unsigned)e << 6) + s * 32 + (m & 1) * 16;
                unsigned swo = sw64(off);
                unsigned b1[4], b2[4];
                ldsm4(b1, wb + swo);            // w term 1
                ldsm4(b2, wb + 4096 + swo);     // w term 2
                if (zstart && s == 0) {
                    mma16816_z(cc[2 * p + 0], a1, b1[0], b1[1]);
                    mma16816_z(cc[2 * p + 1], a1, b1[2], b1[3]);
                } else {
                    mma16816(cc[2 * p + 0], a1, b1[0], b1[1]);
                    mma16816(cc[2 * p + 1], a1, b1[2], b1[3]);
                }
                mma16816(cc[2 * p + 0], a2, b1[0], b1[1]);
                mma16816(cc[2 * p + 1], a2, b1[2], b1[3]);
                mma16816(cc[2 * p + 0], a1, b2[0], b2[1]);
                mma16816(cc[2 * p + 1], a1, b2[2], b2[3]);
            }
        }

        // ---- split+STS x chunk ch+1 into slot (ch+1)%3 (read next iter) ----
        if (ch + 1 < NCH) {
            unsigned xo = ((ch + 1) % 3) * XBUF;
            uint4 t1a, t1b, t2a, t2b;
            split2h(xr[0].x, xr[0].y, t1a.x, t2a.x); split2h(xr[0].z, xr[0].w, t1a.y, t2a.y);
            split2h(xr[1].x, xr[1].y, t1a.z, t2a.z); split2h(xr[1].z, xr[1].w, t1a.w, t2a.w);
            split2h(xr[2].x, xr[2].y, t1b.x, t2b.x); split2h(xr[2].z, xr[2].w, t1b.y, t2b.y);
            split2h(xr[3].x, xr[3].y, t1b.z, t2b.z); split2h(xr[3].z, xr[3].w, t1b.w, t2b.w);
            asm volatile("st.shared.v4.b32 [%0], {%1,%2,%3,%4};" :: "r"(xsts0 + xo),
                         "r"(t1a.x), "r"(t1a.y), "r"(t1a.z), "r"(t1a.w));
            asm volatile("st.shared.v4.b32 [%0], {%1,%2,%3,%4};" :: "r"(xsts1 + xo),
                         "r"(t1b.x), "r"(t1b.y), "r"(t1b.z), "r"(t1b.w));
            asm volatile("st.shared.v4.b32 [%0], {%1,%2,%3,%4};" :: "r"(xsts0 + xo + XT2),
                         "r"(t2a.x), "r"(t2a.y), "r"(t2a.z), "r"(t2a.w));
            asm volatile("st.shared.v4.b32 [%0], {%1,%2,%3,%4};" :: "r"(xsts1 + xo + XT2),
                         "r"(t2b.x), "r"(t2b.y), "r"(t2b.z), "r"(t2b.w));
        }
        // ---- LDG x chunk ch+2 into regs ----
        if (ch + 2 < NCH) {
            const float4* src = xsrc + (size_t)(ch + 2) * 8;
#pragma unroll
            for (int i = 0; i < 4; i++) xr[i] = src[i];
        }

        // ---- drain every 2 chunks: IEEE fp32 adds ----
        if (ch & 1) {
#pragma unroll
            for (int nt = 0; nt < 8; nt++)
#pragma unroll
                for (int i = 0; i < 4; i++) run[nt][i] += cc[nt][i];
        }
    }

    __syncthreads();   // all warps done with mainloop buffers before overlay

    // ---- scatter logits to smem [128][65] (overlays mainloop buffers) ----
    float* lg = (float*)sm;
    const int R0 = wid * 16 + r4;
#pragma unroll
    for (int nt = 0; nt < 8; nt++)
#pragma unroll
        for (int i = 0; i < 4; i++) {
            int tk = R0 + ((i >= 2) ? 8 : 0);
            int ex = nt * 8 + cq * 2 + (i & 1);
            lg[tk * 65 + ex] = run[nt][i];
        }
    __syncthreads();

    if (tid < MT) {
        float sc[NE];
#pragma unroll
        for (int e = 0; e < NE; e++) sc[e] = lg[tid * 65 + e] * WSCALE_INV;  // undo w*32

        float mx = -CUDART_INF_F;
#pragma unroll
        for (int e = 0; e < NE; e++) mx = fmaxf(mx, sc[e]);
        float sum = 0.0f;
#pragma unroll
        for (int e = 0; e < NE; e++) { sc[e] = __expf(sc[e] - mx); sum += sc[e]; }
        float inv = 1.0f / sum;
#pragma unroll
        for (int e = 0; e < NE; e++) sc[e] *= inv;

        const float* bs = (const float*)(sm + OFFB);
        unsigned long long taken = 0ull;
        const int t = t0 + tid;
        float* wout = out + (size_t)t * TOPK;
        float* iout = out + (size_t)TOKENS * TOPK + (size_t)t * TOPK;

#pragma unroll
        for (int sidx = 0; sidx < TOPK; sidx++) {
            float best = -CUDART_INF_F;
            float bsc = 0.0f;
            int be = 0;
#pragma unroll
            for (int e = 0; e < NE; e++) {
                float v = sc[e] + bs[e];
                bool ok = ((taken >> e) & 1ull) == 0ull;
                if (ok && v > best) { best = v; bsc = sc[e]; be = e; }
            }
            taken |= (1ull << be);
            wout[sidx] = bsc;        // ROUTE_SCALE == 1.0
            iout[sidx] = (float)be;
        }
    }
}

extern "C" void kernel_launch(void* const* d_in, const int* in_sizes, int n_in,
                              void* d_out, int out_size) {
    const float* x    = (const float*)d_in[0];
    const float* w    = (const float*)d_in[1];
    const float* bias = (const float*)d_in[2];
    float* out        = (float*)d_out;

    cudaFuncSetAttribute(gate_hmma_kernel,
                         cudaFuncAttributeMaxDynamicSharedMemorySize, SMEMSZ);

    split_w_kernel<<<(NE * DIM) / 256, 256>>>(w);
    gate_hmma_kernel<<<TOKENS / MT, NTH, SMEMSZ>>>(x, bias, out);
}

// round 12
// speedup vs baseline: 1.2309x; 1.2309x over previous
#include <cuda_runtime.h>
#include <cuda_fp16.h>
#include <math_constants.h>
#include <cstdint>

#define TOKENS  32768
#define DIM     2048
#define NE      64
#define TOPK    6
#define MT      128                 // tokens per CTA
#define KCH     64                  // K per chunk (2 x R8 sub-chunks)
#define NCH     (DIM / KCH)         // 32
#define NTH     256
#define WSCALE_INV 0.03125f         // w pre-scaled by 32 in split kernel

// smem map (dynamic): x 2x32KB (2 x 16KB SW128 halves) | w 2x16KB | bias
#define OFFX    0
#define XBUF    32768
#define OFFW    65536
#define WBUF    16384
#define OFFB    98304
#define SMEMSZ  98560

// pre-split (fp16, w*32), pre-swizzled weights: [term][32-chunk][64 experts x 64B]
#define NC32    (DIM / 32)
__device__ __align__(16) unsigned char g_wsw[2][NC32][NE * 32 * 2];

__device__ __forceinline__ unsigned su32(const void* p) {
    return (unsigned)__cvta_generic_to_shared(p);
}
__device__ __forceinline__ void cp16(unsigned d, const void* s) {
    asm volatile("cp.async.cg.shared.global [%0], [%1], 16;" :: "r"(d), "l"(s));
}
// 64B-row XOR swizzle (validated on w tiles): bits[5:4] ^= bits[8:7]
__device__ __forceinline__ unsigned sw64(unsigned off) {
    return off ^ (((off >> 7) & 3u) << 4);
}
// 128B-row swizzle (validated on x tiles): bits[6:4] ^= bits[9:7]
__device__ __forceinline__ unsigned sw128(unsigned off) {
    return off ^ ((off >> 3) & 0x70u);
}
// 2-term fp16 split of (f0,f1): p1 = rn(f), p2 = rn(f - p1)
__device__ __forceinline__ void split2h(float f0, float f1, unsigned& p1, unsigned& p2) {
    __half2 h1 = __floats2half2_rn(f0, f1);
    p1 = *(unsigned*)&h1;
    float2 g = __half22float2(h1);
    __half2 h2 = __floats2half2_rn(f0 - g.x, f1 - g.y);
    p2 = *(unsigned*)&h2;
}
__device__ __forceinline__ void ldsm4(unsigned b[4], unsigned addr) {
    asm volatile("ldmatrix.sync.aligned.m8n8.x4.shared.b16 {%0,%1,%2,%3}, [%4];"
                 : "=r"(b[0]), "=r"(b[1]), "=r"(b[2]), "=r"(b[3]) : "r"(addr));
}
// accumulate: C += A*B (fp16 in, fp32 acc)
__device__ __forceinline__ void mma16816(float* c, const unsigned* a,
                                         unsigned b0, unsigned b1) {
    asm volatile(
        "mma.sync.aligned.m16n8k16.row.col.f32.f16.f16.f32 "
        "{%0,%1,%2,%3}, {%4,%5,%6,%7}, {%8,%9}, {%0,%1,%2,%3};"
        : "+f"(c[0]), "+f"(c[1]), "+f"(c[2]), "+f"(c[3])
        : "r"(a[0]), "r"(a[1]), "r"(a[2]), "r"(a[3]), "r"(b0), "r"(b1));
}
// zero-start: C = A*B
__device__ __forceinline__ void mma16816_z(float* c, const unsigned* a,
                                           unsigned b0, unsigned b1) {
    asm volatile(
        "mma.sync.aligned.m16n8k16.row.col.f32.f16.f16.f32 "
        "{%0,%1,%2,%3}, {%4,%5,%6,%7}, {%8,%9}, {%10,%11,%12,%13};"
        : "=f"(c[0]), "=f"(c[1]), "=f"(c[2]), "=f"(c[3])
        : "r"(a[0]), "r"(a[1]), "r"(a[2]), "r"(a[3]), "r"(b0), "r"(b1),
          "f"(0.0f), "f"(0.0f), "f"(0.0f), "f"(0.0f));
}

// ---- pre-kernel: 2-term fp16 split of 32*w, ldmatrix-swizzled rows of 64B ----
__global__ void split_w_kernel(const float* __restrict__ w) {
    int idx = blockIdx.x * 256 + threadIdx.x;     // e*DIM + k, < 131072
    int e = idx >> 11, k = idx & (DIM - 1);
    float v = w[idx] * 32.0f;                     // exact scale, undone in epilogue
    __half h1 = __float2half_rn(v);
    float f1 = __half2float(h1);
    __half h2 = __float2half_rn(v - f1);
    int c = k >> 5, kk = k & 31;
    unsigned off = ((unsigned)e << 6) | ((unsigned)kk << 1);
    unsigned sw = sw64(off);
    *(unsigned short*)&g_wsw[0][c][sw] = *(unsigned short*)&h1;
    *(unsigned short*)&g_wsw[1][c][sw] = *(unsigned short*)&h2;
}

__global__ __launch_bounds__(NTH, 2)
void gate_hmma_kernel(const float* __restrict__ x,
                      const float* __restrict__ bias,
                      float* __restrict__ out) {
    extern __shared__ unsigned char sm[];

    const int tid = threadIdx.x;
    const int wid = tid >> 5;
    const int L   = tid & 31;
    const int r4  = L >> 2;          // 0..7
    const int cq  = L & 3;           // 0..3
    const int t0  = blockIdx.x * MT;

    if (tid < NE) ((float*)(sm + OFFB))[tid] = bias[tid];

    // ---- x cp.async: thread covers q=(tid&7), rows (tid>>3)+{0,32,64,96}, kb 0..1 ----
    // unit i (0..7): kb = i>>2, rowgroup = i&3
    const float* xp = x + (size_t)(t0 + (tid >> 3)) * DIM + (tid & 7) * 4;
    unsigned offx0 = (unsigned)((tid >> 3) << 7) | (unsigned)((tid & 7) << 4);
    const unsigned xsw0 = sw128(offx0);          // row bits[0:2] invariant under +32
    const unsigned xdst0 = su32(sm + OFFX) + xsw0;

    // ---- w cp.async: block i (0..3): kb = i>>1, term = i&1; one 16B unit/thread ----
    const unsigned char* wp[4];
#pragma unroll
    for (int i = 0; i < 4; i++)
        wp[i] = &g_wsw[i & 1][i >> 1][tid << 4];
    const unsigned wdst0 = su32(sm + OFFW) + (tid << 4);

    // fp32 running logits; one drain per chunk (chain depth 12, validated)
    float run[8][4];
#pragma unroll
    for (int n = 0; n < 8; n++)
#pragma unroll
        for (int i = 0; i < 4; i++) run[n][i] = 0.0f;

    // ---- prologue: chunk 0 -> slot 0 ----
#pragma unroll
    for (int i = 0; i < 8; i++)
        cp16(xdst0 + (i >> 2) * 16384 + (i & 3) * 4096, xp + (i & 3) * 32 * DIM + (i >> 2) * 32);
    xp += KCH;
#pragma unroll
    for (int i = 0; i < 4; i++)
        cp16(wdst0 + (i >> 1) * 8192 + (i & 1) * 4096, wp[i]);
    asm volatile("cp.async.commit_group;");

    const int R0 = wid * 16 + r4;
    const int m  = L >> 3;
    const int rr = L & 7;

    for (int ch = 0; ch < NCH; ch++) {
        asm volatile("cp.async.wait_group 0;");
        __syncthreads();   // chunk ch visible everywhere; slot ch-1 reads all done

        // prefetch chunk ch+1 into the other slot (full compute window to land)
        if (ch + 1 < NCH) {
            unsigned sl = (unsigned)((ch + 1) & 1);
#pragma unroll
            for (int i = 0; i < 8; i++)
                cp16(xdst0 + sl * XBUF + (i >> 2) * 16384 + (i & 3) * 4096,
                     xp + (i & 3) * 32 * DIM + (i >> 2) * 32);
            xp += KCH;
#pragma unroll
            for (int i = 0; i < 4; i++) {
                cp16(wdst0 + sl * WBUF + (i >> 1) * 8192 + (i & 1) * 4096,
                     wp[i] + (size_t)(ch + 1) * 8192);
            }
            asm volatile("cp.async.commit_group;");
        }

        const unsigned xb = su32(sm + OFFX) + (ch & 1) * XBUF;
        const unsigned wb = su32(sm + OFFW) + (ch & 1) * WBUF;

        float cc[8][4];                      // chunk-local tensor-core chains
#pragma unroll
        for (int s = 0; s < 4; s++) {        // four k16 steps per chunk
            const unsigned xkb = xb + (s >> 1) * 16384;
            const unsigned wkb = wb + (s >> 1) * 8192;
            const int sp = s & 1;

            // ---- A fragments: LDS pairs + 2-term fp16 split (R8-validated) ----
            unsigned a1[4], a2[4];
#pragma unroll
            for (int half = 0; half < 2; half++) {
#pragma unroll
                for (int rowi = 0; rowi < 2; rowi++) {
                    int row = R0 + rowi * 8;
                    unsigned off = ((unsigned)row << 7)
                                 + ((unsigned)(sp * 16 + cq * 2 + half * 8) << 2);
                    float f0, f1;
                    asm volatile("ld.shared.v2.f32 {%0,%1}, [%2];"
                                 : "=f"(f0), "=f"(f1) : "r"(xkb + sw128(off)));
                    int pi = half * 2 + rowi;
                    split2h(f0, f1, a1[pi], a2[pi]);
                }
            }
            // ---- B terms + HMMA: 3 products per C per k-step ----
#pragma unroll
            for (int p = 0; p < 4; p++) {
                int e = p * 16 + (m >> 1) * 8 + rr;
                unsigned off = ((unsigned)e << 6) + sp * 32 + (m & 1) * 16;
                unsigned swo = sw64(off);
                unsigned b1[4], b2[4];
                ldsm4(b1, wkb + swo);            // w term 1
                ldsm4(b2, wkb + 4096 + swo);     // w term 2
                if (s == 0) {
                    mma16816_z(cc[2 * p + 0], a1, b1[0], b1[1]);
                    mma16816_z(cc[2 * p + 1], a1, b1[2], b1[3]);
                } else {
                    mma16816(cc[2 * p + 0], a1, b1[0], b1[1]);
                    mma16816(cc[2 * p + 1], a1, b1[2], b1[3]);
                }
                mma16816(cc[2 * p + 0], a2, b1[0], b1[1]);
                mma16816(cc[2 * p + 1], a2, b1[2], b1[3]);
                mma16816(cc[2 * p + 0], a1, b2[0], b2[1]);
                mma16816(cc[2 * p + 1], a1, b2[2], b2[3]);
            }
        }
        // ---- drain once per chunk: IEEE fp32 adds ----
#pragma unroll
        for (int nt = 0; nt < 8; nt++)
#pragma unroll
            for (int i = 0; i < 4; i++) run[nt][i] += cc[nt][i];
    }

    __syncthreads();   // all warps done with mainloop buffers before overlay

    // ---- scatter logits to smem [128][65] (overlays mainloop buffers) ----
    float* lg = (float*)sm;
#pragma unroll
    for (int nt = 0; nt < 8; nt++)
#pragma unroll
        for (int i = 0; i < 4; i++) {
            int tk = R0 + ((i >= 2) ? 8 : 0);
            int ex = nt * 8 + cq * 2 + (i & 1);
            lg[tk * 65 + ex] = run[nt][i];
        }
    __syncthreads();

    if (tid < MT) {
        float sc[NE];
#pragma unroll
        for (int e = 0; e < NE; e++) sc[e] = lg[tid * 65 + e] * WSCALE_INV;  // undo w*32

        float mx = -CUDART_INF_F;
#pragma unroll
        for (int e = 0; e < NE; e++) mx = fmaxf(mx, sc[e]);
        float sum = 0.0f;
#pragma unroll
        for (int e = 0; e < NE; e++) { sc[e] = __expf(sc[e] - mx); sum += sc[e]; }
        float inv = 1.0f / sum;
#pragma unroll
        for (int e = 0; e < NE; e++) sc[e] *= inv;

        const float* bs = (const float*)(sm + OFFB);
        unsigned long long taken = 0ull;
        const int t = t0 + tid;
        float* wout = out + (size_t)t * TOPK;
        float* iout = out + (size_t)TOKENS * TOPK + (size_t)t * TOPK;

#pragma unroll
        for (int sidx = 0; sidx < TOPK; sidx++) {
            float best = -CUDART_INF_F;
            float bsc = 0.0f;
            int be = 0;
#pragma unroll
            for (int e = 0; e < NE; e++) {
                float v = sc[e] + bs[e];
                bool ok = ((taken >> e) & 1ull) == 0ull;
                if (ok && v > best) { best = v; bsc = sc[e]; be = e; }
            }
            taken |= (1ull << be);
            wout[sidx] = bsc;        // ROUTE_SCALE == 1.0
            iout[sidx] = (float)be;
        }
    }
}

extern "C" void kernel_launch(void* const* d_in, const int* in_sizes, int n_in,
                              void* d_out, int out_size) {
    const float* x    = (const float*)d_in[0];
    const float* w    = (const float*)d_in[1];
    const float* bias = (const float*)d_in[2];
    float* out        = (float*)d_out;

    cudaFuncSetAttribute(gate_hmma_kernel,
                         cudaFuncAttributeMaxDynamicSharedMemorySize, SMEMSZ);

    split_w_kernel<<<(NE * DIM) / 256, 256>>>(w);
    gate_hmma_kernel<<<TOKENS / MT, NTH, SMEMSZ>>>(x, bias, out);
}